// round 11
// baseline (speedup 1.0000x reference)
#include <cuda_runtime.h>
#include <cuda_fp16.h>
#include <math.h>
#include <stdint.h>

#define S_DIM 200
#define H_DIM 128
#define F_DIM 512
#define NH 4
#define ATTP 208
#define NT 512
#define NWARP_C 13            // compute warps; warps 13-15 produce
#define BUFQ 32768            // one quarter fp16 fragment buffer (64 blocks * 512B)

// smem: [buf0 0..32K][buf1 32K..64K][W2 float4 8K][atts 2x][outb 2x]
#define SM_W2    65536
#define SM_ATT   (SM_W2 + 8192)          // 2 * 4 * 208 floats = 6656 B
#define SM_OUTB  (SM_ATT + 6656)         // 2 * 512 floats = 4096 B
#define SM_TOTAL (SM_OUTB + 4096)        // 84480 B

static __device__ __forceinline__ uint32_t smem_u32(const void* p) {
    uint32_t a;
    asm("{ .reg .u64 t; cvta.to.shared.u64 t, %1; cvt.u32.u64 %0, t; }" : "=r"(a) : "l"(p));
    return a;
}
static __device__ __forceinline__ uint32_t h2pack(float lo, float hi) {
    __half2 h = __floats2half2_rn(lo, hi);
    return *(uint32_t*)&h;
}
static __device__ __forceinline__ float fast_tanh(float x) {
    float r; asm("tanh.approx.f32 %0, %1;" : "=f"(r) : "f"(x));
    return r;
}
static __device__ __forceinline__ void mma_f16(float* c, const uint32_t* a,
                                               uint32_t b0, uint32_t b1) {
    asm volatile(
        "mma.sync.aligned.m16n8k16.row.col.f32.f16.f16.f32 "
        "{%0,%1,%2,%3}, {%4,%5,%6,%7}, {%8,%9}, {%0,%1,%2,%3};"
        : "+f"(c[0]), "+f"(c[1]), "+f"(c[2]), "+f"(c[3])
        : "r"(a[0]), "r"(a[1]), "r"(a[2]), "r"(a[3]), "r"(b0), "r"(b1));
}

// ---- Producer: stage one W1 quarter (fp16 fragments), layout as R9/R10.
static __device__ __forceinline__ void produce_quarter(const float* __restrict__ W1,
                                                       int qcol, uint32_t bufb,
                                                       int pwid, int lane, int g, int t) {
    #pragma unroll 2
    for (int blk = pwid; blk < 64; blk += 3) {
        int npair = blk >> 3, kf = blk & 7;
        const float* p = W1 + (size_t)(kf * 16 + 2 * t) * F_DIM + qcol + npair * 16 + g;
        float a0 = p[0],             b0 = p[F_DIM];
        float c0 = p[8 * F_DIM],     d0 = p[9 * F_DIM];
        float a1 = p[8],             b1 = p[F_DIM + 8];
        float c1 = p[8 * F_DIM + 8], d1 = p[9 * F_DIM + 8];
        uint32_t w0 = h2pack(a0, b0), w1 = h2pack(c0, d0);
        uint32_t w2 = h2pack(a1, b1), w3 = h2pack(c1, d1);
        asm volatile("st.shared.v4.b32 [%0], {%1,%2,%3,%4};"
                     :: "r"(bufb + (uint32_t)blk * 512 + (uint32_t)lane * 16),
                        "r"(w0), "r"(w1), "r"(w2), "r"(w3));
    }
}

// ---- Consumer: one pair of half-sweeps (32 N-cols) for both batches.
// 8 independent accumulator chains -> dependent HMMA distance ~10 issue slots.
static __device__ __forceinline__ void sweep_pair(uint32_t bq, int q, int hp,
                                                  const uint32_t A[2][8][4],
                                                  float att[2][2][4],
                                                  const float* __restrict__ w2s,
                                                  int lane, int t) {
    float acc[2][2][2][4];   // [hs][batch][ntile][4]
    #pragma unroll
    for (int hs = 0; hs < 2; hs++)
        #pragma unroll
        for (int bb = 0; bb < 2; bb++)
            #pragma unroll
            for (int nf = 0; nf < 2; nf++)
                #pragma unroll
                for (int i = 0; i < 4; i++) acc[hs][bb][nf][i] = 0.0f;

    uint32_t base0 = bq + (uint32_t)(hp * 16) * 512 + (uint32_t)lane * 16;
    #pragma unroll
    for (int kf = 0; kf < 8; kf++) {
        uint32_t x0, x1, x2, x3, y0, y1, y2, y3;
        uint32_t a0 = base0 + (uint32_t)kf * 512;
        asm volatile("ld.shared.v4.b32 {%0,%1,%2,%3}, [%4];"
                     : "=r"(x0), "=r"(x1), "=r"(x2), "=r"(x3) : "r"(a0));
        asm volatile("ld.shared.v4.b32 {%0,%1,%2,%3}, [%4];"
                     : "=r"(y0), "=r"(y1), "=r"(y2), "=r"(y3) : "r"(a0 + 8 * 512));
        mma_f16(acc[0][0][0], A[0][kf], x0, x1);
        mma_f16(acc[0][0][1], A[0][kf], x2, x3);
        mma_f16(acc[0][1][0], A[1][kf], x0, x1);
        mma_f16(acc[0][1][1], A[1][kf], x2, x3);
        mma_f16(acc[1][0][0], A[0][kf], y0, y1);
        mma_f16(acc[1][0][1], A[0][kf], y2, y3);
        mma_f16(acc[1][1][0], A[1][kf], y0, y1);
        mma_f16(acc[1][1][1], A[1][kf], y2, y3);
    }
    #pragma unroll
    for (int hs = 0; hs < 2; hs++) {
        #pragma unroll
        for (int nf = 0; nf < 2; nf++) {
            int col0 = q * 128 + (hp * 2 + hs) * 16 + nf * 8 + 2 * t;
            float4 wA = ((const float4*)w2s)[col0];
            float4 wB = ((const float4*)w2s)[col0 + 1];
            #pragma unroll
            for (int bb = 0; bb < 2; bb++) {
                #pragma unroll
                for (int rh = 0; rh < 2; rh++) {
                    float h0 = fast_tanh(acc[hs][bb][nf][rh * 2 + 0]);
                    float h1 = fast_tanh(acc[hs][bb][nf][rh * 2 + 1]);
                    att[bb][rh][0] += h0 * wA.x + h1 * wB.x;
                    att[bb][rh][1] += h0 * wA.y + h1 * wB.y;
                    att[bb][rh][2] += h0 * wA.z + h1 * wB.z;
                    att[bb][rh][3] += h0 * wA.w + h1 * wB.w;
                }
            }
        }
    }
}

__global__ __launch_bounds__(NT, 1)
void mha_mma_kernel(const float* __restrict__ item,
                    const int*   __restrict__ mask,
                    const float* __restrict__ pos,
                    const float* __restrict__ W1,
                    const float* __restrict__ W2,
                    float* __restrict__ out)
{
    extern __shared__ char smem[];
    const uint32_t smb = smem_u32(smem);
    float* w2s  = (float*)(smem + SM_W2);
    float* atts = (float*)(smem + SM_ATT);   // [2][NH][ATTP]
    float* outb = (float*)(smem + SM_OUTB);  // [2][512]

    const int tid = threadIdx.x, wid = tid >> 5, lane = tid & 31;
    const int g = lane >> 2, t = lane & 3;
    const int b0 = 2 * blockIdx.x;

    // W2 -> smem (1 float4 per thread)
    ((float4*)w2s)[tid] = ((const float4*)W2)[tid];

    // ---- Phase 0: producers stage quarter 0; consumers hoist A (fp16, both batches) ----
    uint32_t A[2][8][4];
    if (wid >= NWARP_C) {
        produce_quarter(W1, 0, smb, wid - NWARP_C, lane, g, t);
    } else {
        const int r0 = wid * 16 + g;
        const bool hi = (r0 + 8) < S_DIM;
        #pragma unroll
        for (int bb = 0; bb < 2; bb++) {
            const float* ib = item + (size_t)(b0 + bb) * (S_DIM * H_DIM);
            const float2* xr0 = (const float2*)(ib + r0 * 128);
            const float2* pr0 = (const float2*)(pos + r0 * 128);
            const float2* xr1 = (const float2*)(ib + (r0 + 8) * 128);
            const float2* pr1 = (const float2*)(pos + (r0 + 8) * 128);
            #pragma unroll
            for (int kf = 0; kf < 8; kf++) {
                int e0 = kf * 8 + t;
                float2 x0 = xr0[e0], p0 = pr0[e0];
                float2 x2 = xr0[e0 + 4], p2 = pr0[e0 + 4];
                A[bb][kf][0] = h2pack(x0.x + p0.x, x0.y + p0.y);
                A[bb][kf][2] = h2pack(x2.x + p2.x, x2.y + p2.y);
                if (hi) {
                    float2 x1 = xr1[e0], p1 = pr1[e0];
                    float2 x3 = xr1[e0 + 4], p3 = pr1[e0 + 4];
                    A[bb][kf][1] = h2pack(x1.x + p1.x, x1.y + p1.y);
                    A[bb][kf][3] = h2pack(x3.x + p3.x, x3.y + p3.y);
                } else {
                    A[bb][kf][1] = 0u;
                    A[bb][kf][3] = 0u;
                }
            }
        }
    }
    __syncthreads();

    float att[2][2][4];
    #pragma unroll
    for (int bb = 0; bb < 2; bb++)
        #pragma unroll
        for (int rh = 0; rh < 2; rh++)
            #pragma unroll
            for (int k = 0; k < 4; k++) att[bb][rh][k] = 0.0f;

    // ---- Main loop: producers stage q+1 while consumers run 4 sweep-pairs of q ----
    #pragma unroll 1
    for (int q = 0; q < 4; q++) {
        const uint32_t bq = smb + (uint32_t)(q & 1) * BUFQ;
        if (wid >= NWARP_C) {
            if (q < 3)
                produce_quarter(W1, (q + 1) * 128,
                                smb + (uint32_t)((q + 1) & 1) * BUFQ,
                                wid - NWARP_C, lane, g, t);
        } else {
            #pragma unroll 1
            for (int hp = 0; hp < 4; hp++)
                sweep_pair(bq, q, hp, A, att, w2s, lane, t);
        }
        __syncthreads();
    }

    // ---- Phase 3: reduce att over the 4-lane k-group, write atts (both batches) ----
    if (wid < NWARP_C) {
        #pragma unroll
        for (int bb = 0; bb < 2; bb++)
            #pragma unroll
            for (int rh = 0; rh < 2; rh++)
                #pragma unroll
                for (int k = 0; k < 4; k++) {
                    float v = att[bb][rh][k];
                    v += __shfl_xor_sync(0xffffffffu, v, 1);
                    v += __shfl_xor_sync(0xffffffffu, v, 2);
                    if (t == 0) {
                        int s = wid * 16 + rh * 8 + g;
                        if (s < S_DIM) atts[bb * NH * ATTP + k * ATTP + s] = v;
                    }
                }
    }
    __syncthreads();

    // ---- Phase 4: mask + softmax (one warp per (batch, head)) ----
    if (tid < 32 * NH * 2) {
        const int bb = tid >> 7, k = (tid >> 5) & 3, l = tid & 31;
        float* ar = atts + bb * NH * ATTP + k * ATTP;
        const int* mrow = mask + (size_t)(b0 + bb) * S_DIM;
        const float NEGV = -4294967296.0f;
        float mx = -INFINITY;
        for (int s = l; s < S_DIM; s += 32) {
            float v = ar[s];
            if (mrow[s] == 0) v = NEGV;
            ar[s] = v;
            mx = fmaxf(mx, v);
        }
        #pragma unroll
        for (int o = 16; o > 0; o >>= 1) mx = fmaxf(mx, __shfl_xor_sync(0xffffffffu, mx, o));
        float sum = 0.0f;
        for (int s = l; s < S_DIM; s += 32) {
            float e = expf(ar[s] - mx);
            ar[s] = e;
            sum += e;
        }
        #pragma unroll
        for (int o = 16; o > 0; o >>= 1) sum += __shfl_xor_sync(0xffffffffu, sum, o);
        float inv = 1.0f / sum;
        for (int s = l; s < S_DIM; s += 32) ar[s] *= inv;
    }
    __syncthreads();

    // ---- Phase 5: interest; 2 batches x 2 s-slices ----
    {
        const int bb = tid >> 8, rem = tid & 255;
        const int slice = rem >> 7, h = rem & 127;
        const float* ib = item + (size_t)(b0 + bb) * (S_DIM * H_DIM) + h;
        const float* ar = atts + bb * NH * ATTP;
        float a0 = 0.f, a1 = 0.f, a2 = 0.f, a3 = 0.f;
        const int s0 = slice * 100, s1 = s0 + 100;
        #pragma unroll 4
        for (int s = s0; s < s1; s++) {
            float xv = ib[(size_t)s * H_DIM];
            a0 += ar[0 * ATTP + s] * xv;
            a1 += ar[1 * ATTP + s] * xv;
            a2 += ar[2 * ATTP + s] * xv;
            a3 += ar[3 * ATTP + s] * xv;
        }
        if (slice == 1) {
            float* o = outb + bb * 512;
            o[0 * 128 + h] = a0; o[1 * 128 + h] = a1;
            o[2 * 128 + h] = a2; o[3 * 128 + h] = a3;
        }
        __syncthreads();
        if (slice == 0) {
            float* ob = out + (size_t)(b0 + bb) * (NH * H_DIM);
            const float* o = outb + bb * 512;
            ob[0 * H_DIM + h] = a0 + o[0 * 128 + h];
            ob[1 * H_DIM + h] = a1 + o[1 * 128 + h];
            ob[2 * H_DIM + h] = a2 + o[2 * 128 + h];
            ob[3 * H_DIM + h] = a3 + o[3 * 128 + h];
        }
    }
}

extern "C" void kernel_launch(void* const* d_in, const int* in_sizes, int n_in,
                              void* d_out, int out_size)
{
    const float* item = (const float*)d_in[0];
    const int*   mask = (const int*)  d_in[1];
    const float* pos  = (const float*)d_in[2];
    const float* W1   = (const float*)d_in[3];
    const float* W2   = (const float*)d_in[4];
    float* out = (float*)d_out;

    const int B = in_sizes[0] / (S_DIM * H_DIM);

    cudaFuncSetAttribute(mha_mma_kernel,
                         cudaFuncAttributeMaxDynamicSharedMemorySize, SM_TOTAL);
    mha_mma_kernel<<<B / 2, NT, SM_TOTAL>>>(item, mask, pos, W1, W2, out);
}

// round 13
// speedup vs baseline: 1.1982x; 1.1982x over previous
#include <cuda_runtime.h>
#include <cuda_fp16.h>
#include <math.h>
#include <stdint.h>

#define S_DIM 200
#define H_DIM 128
#define F_DIM 512
#define NH 4
#define ATTP 208
#define NT 512
#define NWARP_C 13            // compute warps; warps 13-15 produce
#define BUFQ 32768            // one quarter fp16 fragment buffer (64 blocks * 512B)

// smem: [buf0 0..32K][buf1 32K..64K][W2 n8k16 frags 8K][atts 2x][outb 2x]
#define SM_W2F   65536                   // 32 fc * 256 B = 8192
#define SM_ATT   (SM_W2F + 8192)         // 2 * 4 * 208 floats = 6656 B
#define SM_OUTB  (SM_ATT + 6656)         // 2 * 512 floats = 4096 B
#define SM_TOTAL (SM_OUTB + 4096)        // 84480 B

static __device__ __forceinline__ uint32_t smem_u32(const void* p) {
    uint32_t a;
    asm("{ .reg .u64 t; cvta.to.shared.u64 t, %1; cvt.u32.u64 %0, t; }" : "=r"(a) : "l"(p));
    return a;
}
static __device__ __forceinline__ uint32_t h2pack(float lo, float hi) {
    __half2 h = __floats2half2_rn(lo, hi);
    return *(uint32_t*)&h;
}
static __device__ __forceinline__ float fast_tanh(float x) {
    float r; asm("tanh.approx.f32 %0, %1;" : "=f"(r) : "f"(x));
    return r;
}
static __device__ __forceinline__ void mma_f16(float* c, const uint32_t* a,
                                               uint32_t b0, uint32_t b1) {
    asm volatile(
        "mma.sync.aligned.m16n8k16.row.col.f32.f16.f16.f32 "
        "{%0,%1,%2,%3}, {%4,%5,%6,%7}, {%8,%9}, {%0,%1,%2,%3};"
        : "+f"(c[0]), "+f"(c[1]), "+f"(c[2]), "+f"(c[3])
        : "r"(a[0]), "r"(a[1]), "r"(a[2]), "r"(a[3]), "r"(b0), "r"(b1));
}

// ---- Producer: stage one W1 quarter (fp16 fragments), layout as R9/R10.
static __device__ __forceinline__ void produce_quarter(const float* __restrict__ W1,
                                                       int qcol, uint32_t bufb,
                                                       int pwid, int lane, int g, int t) {
    #pragma unroll 2
    for (int blk = pwid; blk < 64; blk += 3) {
        int npair = blk >> 3, kf = blk & 7;
        const float* p = W1 + (size_t)(kf * 16 + 2 * t) * F_DIM + qcol + npair * 16 + g;
        float a0 = p[0],             b0 = p[F_DIM];
        float c0 = p[8 * F_DIM],     d0 = p[9 * F_DIM];
        float a1 = p[8],             b1 = p[F_DIM + 8];
        float c1 = p[8 * F_DIM + 8], d1 = p[9 * F_DIM + 8];
        uint32_t w0 = h2pack(a0, b0), w1 = h2pack(c0, d0);
        uint32_t w2 = h2pack(a1, b1), w3 = h2pack(c1, d1);
        asm volatile("st.shared.v4.b32 [%0], {%1,%2,%3,%4};"
                     :: "r"(bufb + (uint32_t)blk * 512 + (uint32_t)lane * 16),
                        "r"(w0), "r"(w1), "r"(w2), "r"(w3));
    }
}

// ---- Consumer: one half-sweep (16 N-cols = one f-chunk fc) for both batches.
// Epilogue: tanh(acc) repacked as m16n8k16 A fragment, W2 as B fragment -> 1 MMA/batch.
static __device__ __forceinline__ void sweep_half(uint32_t bq, uint32_t w2fb,
                                                  int fc, int hs,
                                                  const uint32_t A[2][8][4],
                                                  float attC[2][4],
                                                  int lane) {
    float acc[2][2][4];   // [batch][ntile][4]
    #pragma unroll
    for (int bb = 0; bb < 2; bb++)
        #pragma unroll
        for (int nf = 0; nf < 2; nf++)
            #pragma unroll
            for (int i = 0; i < 4; i++) acc[bb][nf][i] = 0.0f;

    uint32_t base = bq + (uint32_t)(hs * 8) * 512 + (uint32_t)lane * 16;
    #pragma unroll
    for (int kf = 0; kf < 8; kf++) {
        uint32_t x0, x1, x2, x3;
        asm volatile("ld.shared.v4.b32 {%0,%1,%2,%3}, [%4];"
                     : "=r"(x0), "=r"(x1), "=r"(x2), "=r"(x3)
                     : "r"(base + (uint32_t)kf * 512));
        mma_f16(acc[0][0], A[0][kf], x0, x1);
        mma_f16(acc[0][1], A[0][kf], x2, x3);
        mma_f16(acc[1][0], A[1][kf], x0, x1);
        mma_f16(acc[1][1], A[1][kf], x2, x3);
    }

    // W2 B fragment for this fc (n8k16, cols 4..7 zero-padded)
    uint32_t bf0, bf1;
    asm volatile("ld.shared.v2.b32 {%0,%1}, [%2];"
                 : "=r"(bf0), "=r"(bf1)
                 : "r"(w2fb + (uint32_t)fc * 256 + (uint32_t)lane * 8));

    #pragma unroll
    for (int bb = 0; bb < 2; bb++) {
        uint32_t Af[4];
        Af[0] = h2pack(fast_tanh(acc[bb][0][0]), fast_tanh(acc[bb][0][1]));  // row g,   k=2t..
        Af[1] = h2pack(fast_tanh(acc[bb][0][2]), fast_tanh(acc[bb][0][3]));  // row g+8, k=2t..
        Af[2] = h2pack(fast_tanh(acc[bb][1][0]), fast_tanh(acc[bb][1][1]));  // row g,   k=8+2t..
        Af[3] = h2pack(fast_tanh(acc[bb][1][2]), fast_tanh(acc[bb][1][3]));  // row g+8, k=8+2t..
        mma_f16(attC[bb], Af, bf0, bf1);
    }
}

__global__ __launch_bounds__(NT, 1)
void mha_mma_kernel(const float* __restrict__ item,
                    const int*   __restrict__ mask,
                    const float* __restrict__ pos,
                    const float* __restrict__ W1,
                    const float* __restrict__ W2,
                    float* __restrict__ out)
{
    extern __shared__ char smem[];
    const uint32_t smb = smem_u32(smem);
    float* atts = (float*)(smem + SM_ATT);   // [2][NH][ATTP]
    float* outb = (float*)(smem + SM_OUTB);  // [2][512]

    const int tid = threadIdx.x, wid = tid >> 5, lane = tid & 31;
    const int g = lane >> 2, t = lane & 3;
    const int b0 = 2 * blockIdx.x;
    const uint32_t w2fb = smb + SM_W2F;

    // ---- W2 -> n8k16 B-fragment buffer (warp w handles fc = 2w, 2w+1) ----
    {
        #pragma unroll
        for (int i = 0; i < 2; i++) {
            int fc = wid * 2 + i;
            float w0a = 0.f, w0b = 0.f, w1a = 0.f, w1b = 0.f;
            if (g < NH) {
                int fb = fc * 16;
                w0a = W2[(fb + 2 * t) * NH + g];
                w0b = W2[(fb + 2 * t + 1) * NH + g];
                w1a = W2[(fb + 8 + 2 * t) * NH + g];
                w1b = W2[(fb + 9 + 2 * t) * NH + g];
            }
            uint32_t f0 = h2pack(w0a, w0b), f1 = h2pack(w1a, w1b);
            asm volatile("st.shared.v2.b32 [%0], {%1,%2};"
                         :: "r"(w2fb + (uint32_t)fc * 256 + (uint32_t)lane * 8),
                            "r"(f0), "r"(f1));
        }
    }

    // ---- Phase 0: producers stage quarter 0; consumers hoist A (fp16, both batches) ----
    uint32_t A[2][8][4];
    if (wid >= NWARP_C) {
        produce_quarter(W1, 0, smb, wid - NWARP_C, lane, g, t);
    } else {
        const int r0 = wid * 16 + g;
        const bool hi = (r0 + 8) < S_DIM;
        #pragma unroll
        for (int bb = 0; bb < 2; bb++) {
            const float* ib = item + (size_t)(b0 + bb) * (S_DIM * H_DIM);
            const float2* xr0 = (const float2*)(ib + r0 * 128);
            const float2* pr0 = (const float2*)(pos + r0 * 128);
            const float2* xr1 = (const float2*)(ib + (r0 + 8) * 128);
            const float2* pr1 = (const float2*)(pos + (r0 + 8) * 128);
            #pragma unroll
            for (int kf = 0; kf < 8; kf++) {
                int e0 = kf * 8 + t;
                float2 x0 = xr0[e0], p0 = pr0[e0];
                float2 x2 = xr0[e0 + 4], p2 = pr0[e0 + 4];
                A[bb][kf][0] = h2pack(x0.x + p0.x, x0.y + p0.y);
                A[bb][kf][2] = h2pack(x2.x + p2.x, x2.y + p2.y);
                if (hi) {
                    float2 x1 = xr1[e0], p1 = pr1[e0];
                    float2 x3 = xr1[e0 + 4], p3 = pr1[e0 + 4];
                    A[bb][kf][1] = h2pack(x1.x + p1.x, x1.y + p1.y);
                    A[bb][kf][3] = h2pack(x3.x + p3.x, x3.y + p3.y);
                } else {
                    A[bb][kf][1] = 0u;
                    A[bb][kf][3] = 0u;
                }
            }
        }
    }
    __syncthreads();

    // att as m16n8 C fragments: rows = s (warp's mtile), cols = heads (0..3 valid)
    float attC[2][4];
    #pragma unroll
    for (int bb = 0; bb < 2; bb++)
        #pragma unroll
        for (int i = 0; i < 4; i++) attC[bb][i] = 0.0f;

    // ---- Main loop: producers stage q+1 while consumers run 8 half-sweeps of q ----
    #pragma unroll 1
    for (int q = 0; q < 4; q++) {
        const uint32_t bq = smb + (uint32_t)(q & 1) * BUFQ;
        if (wid >= NWARP_C) {
            if (q < 3)
                produce_quarter(W1, (q + 1) * 128,
                                smb + (uint32_t)((q + 1) & 1) * BUFQ,
                                wid - NWARP_C, lane, g, t);
        } else {
            #pragma unroll 1
            for (int hs = 0; hs < 8; hs++)
                sweep_half(bq, w2fb, q * 8 + hs, hs, A, attC, lane);
        }
        __syncthreads();
    }

    // ---- Phase 3: write att directly from C fragments (no shuffles; t<2 hold heads 0..3) ----
    if (wid < NWARP_C && t < 2) {
        const int s = wid * 16 + g;
        #pragma unroll
        for (int bb = 0; bb < 2; bb++) {
            float* ab = atts + bb * NH * ATTP;
            if (s < S_DIM) {
                ab[(2 * t) * ATTP + s]     = attC[bb][0];
                ab[(2 * t + 1) * ATTP + s] = attC[bb][1];
            }
            if (s + 8 < S_DIM) {
                ab[(2 * t) * ATTP + s + 8]     = attC[bb][2];
                ab[(2 * t + 1) * ATTP + s + 8] = attC[bb][3];
            }
        }
    }
    __syncthreads();

    // ---- Phase 4: mask + softmax (one warp per (batch, head)) ----
    if (tid < 32 * NH * 2) {
        const int bb = tid >> 7, k = (tid >> 5) & 3, l = tid & 31;
        float* ar = atts + bb * NH * ATTP + k * ATTP;
        const int* mrow = mask + (size_t)(b0 + bb) * S_DIM;
        const float NEGV = -4294967296.0f;
        float mx = -INFINITY;
        for (int s = l; s < S_DIM; s += 32) {
            float v = ar[s];
            if (mrow[s] == 0) v = NEGV;
            ar[s] = v;
            mx = fmaxf(mx, v);
        }
        #pragma unroll
        for (int o = 16; o > 0; o >>= 1) mx = fmaxf(mx, __shfl_xor_sync(0xffffffffu, mx, o));
        float sum = 0.0f;
        for (int s = l; s < S_DIM; s += 32) {
            float e = expf(ar[s] - mx);
            ar[s] = e;
            sum += e;
        }
        #pragma unroll
        for (int o = 16; o > 0; o >>= 1) sum += __shfl_xor_sync(0xffffffffu, sum, o);
        float inv = 1.0f / sum;
        for (int s = l; s < S_DIM; s += 32) ar[s] *= inv;
    }
    __syncthreads();

    // ---- Phase 5: interest; 2 batches x 2 s-slices ----
    {
        const int bb = tid >> 8, rem = tid & 255;
        const int slice = rem >> 7, h = rem & 127;
        const float* ib = item + (size_t)(b0 + bb) * (S_DIM * H_DIM) + h;
        const float* ar = atts + bb * NH * ATTP;
        float a0 = 0.f, a1 = 0.f, a2 = 0.f, a3 = 0.f;
        const int s0 = slice * 100, s1 = s0 + 100;
        #pragma unroll 4
        for (int s = s0; s < s1; s++) {
            float xv = ib[(size_t)s * H_DIM];
            a0 += ar[0 * ATTP + s] * xv;
            a1 += ar[1 * ATTP + s] * xv;
            a2 += ar[2 * ATTP + s] * xv;
            a3 += ar[3 * ATTP + s] * xv;
        }
        if (slice == 1) {
            float* o = outb + bb * 512;
            o[0 * 128 + h] = a0; o[1 * 128 + h] = a1;
            o[2 * 128 + h] = a2; o[3 * 128 + h] = a3;
        }
        __syncthreads();
        if (slice == 0) {
            float* ob = out + (size_t)(b0 + bb) * (NH * H_DIM);
            const float* o = outb + bb * 512;
            ob[0 * H_DIM + h] = a0 + o[0 * 128 + h];
            ob[1 * H_DIM + h] = a1 + o[1 * 128 + h];
            ob[2 * H_DIM + h] = a2 + o[2 * 128 + h];
            ob[3 * H_DIM + h] = a3 + o[3 * 128 + h];
        }
    }
}

extern "C" void kernel_launch(void* const* d_in, const int* in_sizes, int n_in,
                              void* d_out, int out_size)
{
    const float* item = (const float*)d_in[0];
    const int*   mask = (const int*)  d_in[1];
    const float* pos  = (const float*)d_in[2];
    const float* W1   = (const float*)d_in[3];
    const float* W2   = (const float*)d_in[4];
    float* out = (float*)d_out;

    const int B = in_sizes[0] / (S_DIM * H_DIM);

    cudaFuncSetAttribute(mha_mma_kernel,
                         cudaFuncAttributeMaxDynamicSharedMemorySize, SM_TOTAL);
    mha_mma_kernel<<<B / 2, NT, SM_TOTAL>>>(item, mask, pos, W1, W2, out);
}

// round 14
// speedup vs baseline: 1.2153x; 1.0142x over previous
#include <cuda_runtime.h>
#include <cuda_fp16.h>
#include <math.h>
#include <stdint.h>

#define S_DIM 200
#define H_DIM 128
#define F_DIM 512
#define NH 4
#define ATTP 208
#define NT 512
#define NWARP_C 13            // compute warps (M-tile = wid); warps 13-15 only help stage

// smem: [W1 frags 128K][W2 n8k16 frags 8K][atts 2x][outb 2x]
#define SM_W2F   131072                  // 32 fc * 256 B = 8192
#define SM_ATT   (SM_W2F + 8192)         // 2 * 4 * 208 floats = 6656 B
#define SM_OUTB  (SM_ATT + 6656)         // 2 * 512 floats = 4096 B
#define SM_TOTAL (SM_OUTB + 4096)        // 150016 B

// W1 in fragment layout, fp16: 256 blocks (blk = fc*8 + kf) * 512 B
__device__ __align__(16) unsigned char gW1f[131072];

static __device__ __forceinline__ uint32_t smem_u32(const void* p) {
    uint32_t a;
    asm("{ .reg .u64 t; cvta.to.shared.u64 t, %1; cvt.u32.u64 %0, t; }" : "=r"(a) : "l"(p));
    return a;
}
static __device__ __forceinline__ uint32_t h2pack(float lo, float hi) {
    __half2 h = __floats2half2_rn(lo, hi);
    return *(uint32_t*)&h;
}
static __device__ __forceinline__ float fast_tanh(float x) {
    float r; asm("tanh.approx.f32 %0, %1;" : "=f"(r) : "f"(x));
    return r;
}
static __device__ __forceinline__ void mma_f16(float* c, const uint32_t* a,
                                               uint32_t b0, uint32_t b1) {
    asm volatile(
        "mma.sync.aligned.m16n8k16.row.col.f32.f16.f16.f32 "
        "{%0,%1,%2,%3}, {%4,%5,%6,%7}, {%8,%9}, {%0,%1,%2,%3};"
        : "+f"(c[0]), "+f"(c[1]), "+f"(c[2]), "+f"(c[3])
        : "r"(a[0]), "r"(a[1]), "r"(a[2]), "r"(a[3]), "r"(b0), "r"(b1));
}

// ---- Prep: W1 f32 [128,512] -> fragment-layout fp16 global buffer.
// blk = fc*8 + kf (fc = 16-col group 0..31, kf = k16-block 0..7);
// lane (g,t) 16B slot = {h2(p[0],p[F]), h2(p[8F],p[9F]), h2(p[8],p[F+8]), h2(p[8F+8],p[9F+8])}
// with p = W1 + (kf*16 + 2t)*F_DIM + fc*16 + g.  (identical numerics to R13 producer)
__global__ void prep_w1_kernel(const float* __restrict__ W1) {
    int idx = blockIdx.x * blockDim.x + threadIdx.x;   // 8192 threads
    int blk = idx >> 5, lane = idx & 31;
    int g = lane >> 2, t = lane & 3;
    int fc = blk >> 3, kf = blk & 7;
    const float* p = W1 + (size_t)(kf * 16 + 2 * t) * F_DIM + fc * 16 + g;
    uint32_t w0 = h2pack(p[0],             p[F_DIM]);
    uint32_t w1 = h2pack(p[8 * F_DIM],     p[9 * F_DIM]);
    uint32_t w2 = h2pack(p[8],             p[F_DIM + 8]);
    uint32_t w3 = h2pack(p[8 * F_DIM + 8], p[9 * F_DIM + 8]);
    ((uint4*)gW1f)[idx] = make_uint4(w0, w1, w2, w3);
}

// ---- Consumer: one half-sweep (16 N-cols = one f-chunk fc) for both batches.
static __device__ __forceinline__ void sweep_half(uint32_t base0, uint32_t w2fb,
                                                  int fc,
                                                  const uint32_t A[2][8][4],
                                                  float attC[2][4],
                                                  int lane) {
    float acc[2][2][4];   // [batch][ntile][4]
    #pragma unroll
    for (int bb = 0; bb < 2; bb++)
        #pragma unroll
        for (int nf = 0; nf < 2; nf++)
            #pragma unroll
            for (int i = 0; i < 4; i++) acc[bb][nf][i] = 0.0f;

    uint32_t base = base0 + (uint32_t)lane * 16;
    #pragma unroll
    for (int kf = 0; kf < 8; kf++) {
        uint32_t x0, x1, x2, x3;
        asm volatile("ld.shared.v4.b32 {%0,%1,%2,%3}, [%4];"
                     : "=r"(x0), "=r"(x1), "=r"(x2), "=r"(x3)
                     : "r"(base + (uint32_t)kf * 512));
        mma_f16(acc[0][0], A[0][kf], x0, x1);
        mma_f16(acc[0][1], A[0][kf], x2, x3);
        mma_f16(acc[1][0], A[1][kf], x0, x1);
        mma_f16(acc[1][1], A[1][kf], x2, x3);
    }

    uint32_t bf0, bf1;
    asm volatile("ld.shared.v2.b32 {%0,%1}, [%2];"
                 : "=r"(bf0), "=r"(bf1)
                 : "r"(w2fb + (uint32_t)fc * 256 + (uint32_t)lane * 8));

    #pragma unroll
    for (int bb = 0; bb < 2; bb++) {
        uint32_t Af[4];
        Af[0] = h2pack(fast_tanh(acc[bb][0][0]), fast_tanh(acc[bb][0][1]));
        Af[1] = h2pack(fast_tanh(acc[bb][0][2]), fast_tanh(acc[bb][0][3]));
        Af[2] = h2pack(fast_tanh(acc[bb][1][0]), fast_tanh(acc[bb][1][1]));
        Af[3] = h2pack(fast_tanh(acc[bb][1][2]), fast_tanh(acc[bb][1][3]));
        mma_f16(attC[bb], Af, bf0, bf1);
    }
}

__global__ __launch_bounds__(NT, 1)
void mha_mma_kernel(const float* __restrict__ item,
                    const int*   __restrict__ mask,
                    const float* __restrict__ pos,
                    const float* __restrict__ W2,
                    float* __restrict__ out)
{
    extern __shared__ char smem[];
    const uint32_t smb = smem_u32(smem);
    float* atts = (float*)(smem + SM_ATT);   // [2][NH][ATTP]
    float* outb = (float*)(smem + SM_OUTB);  // [2][512]

    const int tid = threadIdx.x, wid = tid >> 5, lane = tid & 31;
    const int g = lane >> 2, t = lane & 3;
    const int b0 = 2 * blockIdx.x;
    const uint32_t w2fb = smb + SM_W2F;

    // ---- Stage all of W1 (fragment fp16) via cp.async; fully overlaps A-hoist ----
    {
        const char* gsrc = (const char*)gW1f;
        #pragma unroll
        for (int i = 0; i < 16; i++) {
            uint32_t off = (uint32_t)(i * NT + tid) * 16;
            asm volatile("cp.async.cg.shared.global [%0], [%1], 16;"
                         :: "r"(smb + off), "l"(gsrc + off));
        }
        asm volatile("cp.async.commit_group;" ::: "memory");
    }

    // ---- W2 -> n8k16 B-fragment buffer (warp w handles fc = 2w, 2w+1) ----
    {
        #pragma unroll
        for (int i = 0; i < 2; i++) {
            int fc = wid * 2 + i;
            float w0a = 0.f, w0b = 0.f, w1a = 0.f, w1b = 0.f;
            if (g < NH) {
                int fb = fc * 16;
                w0a = W2[(fb + 2 * t) * NH + g];
                w0b = W2[(fb + 2 * t + 1) * NH + g];
                w1a = W2[(fb + 8 + 2 * t) * NH + g];
                w1b = W2[(fb + 9 + 2 * t) * NH + g];
            }
            uint32_t f0 = h2pack(w0a, w0b), f1 = h2pack(w1a, w1b);
            asm volatile("st.shared.v2.b32 [%0], {%1,%2};"
                         :: "r"(w2fb + (uint32_t)fc * 256 + (uint32_t)lane * 8),
                            "r"(f0), "r"(f1));
        }
    }

    // ---- A fragments from global (fp16, both batches) ----
    uint32_t A[2][8][4];
    if (wid < NWARP_C) {
        const int r0 = wid * 16 + g;
        const bool hi = (r0 + 8) < S_DIM;
        #pragma unroll
        for (int bb = 0; bb < 2; bb++) {
            const float* ib = item + (size_t)(b0 + bb) * (S_DIM * H_DIM);
            const float2* xr0 = (const float2*)(ib + r0 * 128);
            const float2* pr0 = (const float2*)(pos + r0 * 128);
            const float2* xr1 = (const float2*)(ib + (r0 + 8) * 128);
            const float2* pr1 = (const float2*)(pos + (r0 + 8) * 128);
            #pragma unroll
            for (int kf = 0; kf < 8; kf++) {
                int e0 = kf * 8 + t;
                float2 x0 = xr0[e0], p0 = pr0[e0];
                float2 x2 = xr0[e0 + 4], p2 = pr0[e0 + 4];
                A[bb][kf][0] = h2pack(x0.x + p0.x, x0.y + p0.y);
                A[bb][kf][2] = h2pack(x2.x + p2.x, x2.y + p2.y);
                if (hi) {
                    float2 x1 = xr1[e0], p1 = pr1[e0];
                    float2 x3 = xr1[e0 + 4], p3 = pr1[e0 + 4];
                    A[bb][kf][1] = h2pack(x1.x + p1.x, x1.y + p1.y);
                    A[bb][kf][3] = h2pack(x3.x + p3.x, x3.y + p3.y);
                } else {
                    A[bb][kf][1] = 0u;
                    A[bb][kf][3] = 0u;
                }
            }
        }
    }

    asm volatile("cp.async.wait_group 0;" ::: "memory");
    __syncthreads();

    // att as m16n8 C fragments: rows = s, cols = heads (0..3 valid)
    float attC[2][4];
    #pragma unroll
    for (int bb = 0; bb < 2; bb++)
        #pragma unroll
        for (int i = 0; i < 4; i++) attC[bb][i] = 0.0f;

    // ---- Barrier-free mainloop: 32 half-sweeps over the resident W1 ----
    if (wid < NWARP_C) {
        #pragma unroll 1
        for (int fc = 0; fc < 32; fc++)
            sweep_half(smb + (uint32_t)fc * 4096, w2fb, fc, A, attC, lane);
    }

    // ---- Phase 3: write att directly from C fragments (t<2 hold heads 0..3) ----
    if (wid < NWARP_C && t < 2) {
        const int s = wid * 16 + g;
        #pragma unroll
        for (int bb = 0; bb < 2; bb++) {
            float* ab = atts + bb * NH * ATTP;
            if (s < S_DIM) {
                ab[(2 * t) * ATTP + s]     = attC[bb][0];
                ab[(2 * t + 1) * ATTP + s] = attC[bb][1];
            }
            if (s + 8 < S_DIM) {
                ab[(2 * t) * ATTP + s + 8]     = attC[bb][2];
                ab[(2 * t + 1) * ATTP + s + 8] = attC[bb][3];
            }
        }
    }
    __syncthreads();

    // ---- Phase 4: mask + softmax (one warp per (batch, head)) ----
    if (tid < 32 * NH * 2) {
        const int bb = tid >> 7, k = (tid >> 5) & 3, l = tid & 31;
        float* ar = atts + bb * NH * ATTP + k * ATTP;
        const int* mrow = mask + (size_t)(b0 + bb) * S_DIM;
        const float NEGV = -4294967296.0f;
        float mx = -INFINITY;
        for (int s = l; s < S_DIM; s += 32) {
            float v = ar[s];
            if (mrow[s] == 0) v = NEGV;
            ar[s] = v;
            mx = fmaxf(mx, v);
        }
        #pragma unroll
        for (int o = 16; o > 0; o >>= 1) mx = fmaxf(mx, __shfl_xor_sync(0xffffffffu, mx, o));
        float sum = 0.0f;
        for (int s = l; s < S_DIM; s += 32) {
            float e = expf(ar[s] - mx);
            ar[s] = e;
            sum += e;
        }
        #pragma unroll
        for (int o = 16; o > 0; o >>= 1) sum += __shfl_xor_sync(0xffffffffu, sum, o);
        float inv = 1.0f / sum;
        for (int s = l; s < S_DIM; s += 32) ar[s] *= inv;
    }
    __syncthreads();

    // ---- Phase 5: interest; 2 batches x 2 s-slices ----
    {
        const int bb = tid >> 8, rem = tid & 255;
        const int slice = rem >> 7, h = rem & 127;
        const float* ib = item + (size_t)(b0 + bb) * (S_DIM * H_DIM) + h;
        const float* ar = atts + bb * NH * ATTP;
        float a0 = 0.f, a1 = 0.f, a2 = 0.f, a3 = 0.f;
        const int s0 = slice * 100, s1 = s0 + 100;
        #pragma unroll 4
        for (int s = s0; s < s1; s++) {
            float xv = ib[(size_t)s * H_DIM];
            a0 += ar[0 * ATTP + s] * xv;
            a1 += ar[1 * ATTP + s] * xv;
            a2 += ar[2 * ATTP + s] * xv;
            a3 += ar[3 * ATTP + s] * xv;
        }
        if (slice == 1) {
            float* o = outb + bb * 512;
            o[0 * 128 + h] = a0; o[1 * 128 + h] = a1;
            o[2 * 128 + h] = a2; o[3 * 128 + h] = a3;
        }
        __syncthreads();
        if (slice == 0) {
            float* ob = out + (size_t)(b0 + bb) * (NH * H_DIM);
            const float* o = outb + bb * 512;
            ob[0 * H_DIM + h] = a0 + o[0 * 128 + h];
            ob[1 * H_DIM + h] = a1 + o[1 * 128 + h];
            ob[2 * H_DIM + h] = a2 + o[2 * 128 + h];
            ob[3 * H_DIM + h] = a3 + o[3 * 128 + h];
        }
    }
}

extern "C" void kernel_launch(void* const* d_in, const int* in_sizes, int n_in,
                              void* d_out, int out_size)
{
    const float* item = (const float*)d_in[0];
    const int*   mask = (const int*)  d_in[1];
    const float* pos  = (const float*)d_in[2];
    const float* W1   = (const float*)d_in[3];
    const float* W2   = (const float*)d_in[4];
    float* out = (float*)d_out;

    const int B = in_sizes[0] / (S_DIM * H_DIM);

    prep_w1_kernel<<<32, 256>>>(W1);

    cudaFuncSetAttribute(mha_mma_kernel,
                         cudaFuncAttributeMaxDynamicSharedMemorySize, SM_TOTAL);
    mha_mma_kernel<<<B / 2, NT, SM_TOTAL>>>(item, mask, pos, W2, out);
}

// round 15
// speedup vs baseline: 1.2227x; 1.0061x over previous
#include <cuda_runtime.h>
#include <cuda_fp16.h>
#include <math.h>
#include <stdint.h>

#define S_DIM 200
#define H_DIM 128
#define F_DIM 512
#define NH 4
#define ATTP 208
#define NT 512

// smem: [W1 frags 128K][W2 n8k16 frags 8K][atts 2x][outb 2x]
#define SM_W2F   131072
#define SM_ATT   (SM_W2F + 8192)
#define SM_OUTB  (SM_ATT + 6656)
#define SM_TOTAL (SM_OUTB + 4096)   // 150016 B

// W1 in fragment layout, fp16: 256 blocks (blk = fc*8 + kf) * 512 B
__device__ __align__(16) unsigned char gW1f[131072];

// Unit tables: unit u in 0..25, bb = u/13 (batch), mt = u%13 (mtile).
// Per-SMSP unit loads: {7,7,6,6} (SMSP = wid & 3).
__constant__ int c_ua[16] = {0,2,4,6,8,10,12,14,16,18,20,22,24,25,21,23};
__constant__ int c_ub[16] = {1,3,5,7,9,11,13,15,17,19,-1,-1,-1,-1,-1,-1};

static __device__ __forceinline__ uint32_t smem_u32(const void* p) {
    uint32_t a;
    asm("{ .reg .u64 t; cvta.to.shared.u64 t, %1; cvt.u32.u64 %0, t; }" : "=r"(a) : "l"(p));
    return a;
}
static __device__ __forceinline__ uint32_t h2pack(float lo, float hi) {
    __half2 h = __floats2half2_rn(lo, hi);
    return *(uint32_t*)&h;
}
static __device__ __forceinline__ float fast_tanh(float x) {
    float r; asm("tanh.approx.f32 %0, %1;" : "=f"(r) : "f"(x));
    return r;
}
static __device__ __forceinline__ void mma_f16(float* c, const uint32_t* a,
                                               uint32_t b0, uint32_t b1) {
    asm volatile(
        "mma.sync.aligned.m16n8k16.row.col.f32.f16.f16.f32 "
        "{%0,%1,%2,%3}, {%4,%5,%6,%7}, {%8,%9}, {%0,%1,%2,%3};"
        : "+f"(c[0]), "+f"(c[1]), "+f"(c[2]), "+f"(c[3])
        : "r"(a[0]), "r"(a[1]), "r"(a[2]), "r"(a[3]), "r"(b0), "r"(b1));
}

// ---- Prep: W1 f32 [128,512] -> fragment-layout fp16 global buffer (as R14).
__global__ void prep_w1_kernel(const float* __restrict__ W1) {
    int idx = blockIdx.x * blockDim.x + threadIdx.x;   // 8192 threads
    int blk = idx >> 5, lane = idx & 31;
    int g = lane >> 2, t = lane & 3;
    int fc = blk >> 3, kf = blk & 7;
    const float* p = W1 + (size_t)(kf * 16 + 2 * t) * F_DIM + fc * 16 + g;
    uint32_t w0 = h2pack(p[0],             p[F_DIM]);
    uint32_t w1 = h2pack(p[8 * F_DIM],     p[9 * F_DIM]);
    uint32_t w2 = h2pack(p[8],             p[F_DIM + 8]);
    uint32_t w3 = h2pack(p[8 * F_DIM + 8], p[9 * F_DIM + 8]);
    ((uint4*)gW1f)[idx] = make_uint4(w0, w1, w2, w3);
}

// ---- Hoist A fragments for one unit (batch bb rows mt*16..+15) from global.
static __device__ __forceinline__ void hoist_A(uint32_t A[8][4],
                                               const float* __restrict__ item,
                                               const float* __restrict__ pos,
                                               int b, int mt, int g, int t) {
    const int r0 = mt * 16 + g;
    const bool hi = (r0 + 8) < S_DIM;
    const float* ib = item + (size_t)b * (S_DIM * H_DIM);
    const float2* xr0 = (const float2*)(ib + r0 * 128);
    const float2* pr0 = (const float2*)(pos + r0 * 128);
    const float2* xr1 = (const float2*)(ib + (r0 + 8) * 128);
    const float2* pr1 = (const float2*)(pos + (r0 + 8) * 128);
    #pragma unroll
    for (int kf = 0; kf < 8; kf++) {
        int e0 = kf * 8 + t;
        float2 x0 = xr0[e0], p0 = pr0[e0];
        float2 x2 = xr0[e0 + 4], p2 = pr0[e0 + 4];
        A[kf][0] = h2pack(x0.x + p0.x, x0.y + p0.y);
        A[kf][2] = h2pack(x2.x + p2.x, x2.y + p2.y);
        if (hi) {
            float2 x1 = xr1[e0], p1 = pr1[e0];
            float2 x3 = xr1[e0 + 4], p3 = pr1[e0 + 4];
            A[kf][1] = h2pack(x1.x + p1.x, x1.y + p1.y);
            A[kf][3] = h2pack(x3.x + p3.x, x3.y + p3.y);
        } else {
            A[kf][1] = 0u;
            A[kf][3] = 0u;
        }
    }
}

// ---- One half-sweep (16 N-cols = one f-chunk fc) for NU units.
template<int NU>
static __device__ __forceinline__ void sweep_half(uint32_t base0, uint32_t w2fb,
                                                  int fc,
                                                  const uint32_t A[2][8][4],
                                                  float attC[2][4],
                                                  int lane) {
    float acc[NU][2][4];
    #pragma unroll
    for (int u = 0; u < NU; u++)
        #pragma unroll
        for (int nf = 0; nf < 2; nf++)
            #pragma unroll
            for (int i = 0; i < 4; i++) acc[u][nf][i] = 0.0f;

    uint32_t base = base0 + (uint32_t)lane * 16;
    #pragma unroll
    for (int kf = 0; kf < 8; kf++) {
        uint32_t x0, x1, x2, x3;
        asm volatile("ld.shared.v4.b32 {%0,%1,%2,%3}, [%4];"
                     : "=r"(x0), "=r"(x1), "=r"(x2), "=r"(x3)
                     : "r"(base + (uint32_t)kf * 512));
        #pragma unroll
        for (int u = 0; u < NU; u++) {
            mma_f16(acc[u][0], A[u][kf], x0, x1);
            mma_f16(acc[u][1], A[u][kf], x2, x3);
        }
    }

    uint32_t bf0, bf1;
    asm volatile("ld.shared.v2.b32 {%0,%1}, [%2];"
                 : "=r"(bf0), "=r"(bf1)
                 : "r"(w2fb + (uint32_t)fc * 256 + (uint32_t)lane * 8));

    #pragma unroll
    for (int u = 0; u < NU; u++) {
        uint32_t Af[4];
        Af[0] = h2pack(fast_tanh(acc[u][0][0]), fast_tanh(acc[u][0][1]));
        Af[1] = h2pack(fast_tanh(acc[u][0][2]), fast_tanh(acc[u][0][3]));
        Af[2] = h2pack(fast_tanh(acc[u][1][0]), fast_tanh(acc[u][1][1]));
        Af[3] = h2pack(fast_tanh(acc[u][1][2]), fast_tanh(acc[u][1][3]));
        mma_f16(attC[u], Af, bf0, bf1);
    }
}

__global__ __launch_bounds__(NT, 1)
void mha_mma_kernel(const float* __restrict__ item,
                    const int*   __restrict__ mask,
                    const float* __restrict__ pos,
                    const float* __restrict__ W2,
                    float* __restrict__ out)
{
    extern __shared__ char smem[];
    const uint32_t smb = smem_u32(smem);
    float* atts = (float*)(smem + SM_ATT);   // [2][NH][ATTP]
    float* outb = (float*)(smem + SM_OUTB);  // [2][512]

    const int tid = threadIdx.x, wid = tid >> 5, lane = tid & 31;
    const int g = lane >> 2, t = lane & 3;
    const int b0 = 2 * blockIdx.x;
    const uint32_t w2fb = smb + SM_W2F;

    const int ua = c_ua[wid], ub = c_ub[wid];
    const int nu = (ub >= 0) ? 2 : 1;

    // ---- Stage all of W1 (fragment fp16) via cp.async; overlaps A-hoist ----
    {
        const char* gsrc = (const char*)gW1f;
        #pragma unroll
        for (int i = 0; i < 16; i++) {
            uint32_t off = (uint32_t)(i * NT + tid) * 16;
            asm volatile("cp.async.cg.shared.global [%0], [%1], 16;"
                         :: "r"(smb + off), "l"(gsrc + off));
        }
        asm volatile("cp.async.commit_group;" ::: "memory");
    }

    // ---- W2 -> n8k16 B-fragment buffer (warp w handles fc = 2w, 2w+1) ----
    {
        #pragma unroll
        for (int i = 0; i < 2; i++) {
            int fc = wid * 2 + i;
            float w0a = 0.f, w0b = 0.f, w1a = 0.f, w1b = 0.f;
            if (g < NH) {
                int fb = fc * 16;
                w0a = W2[(fb + 2 * t) * NH + g];
                w0b = W2[(fb + 2 * t + 1) * NH + g];
                w1a = W2[(fb + 8 + 2 * t) * NH + g];
                w1b = W2[(fb + 9 + 2 * t) * NH + g];
            }
            uint32_t f0 = h2pack(w0a, w0b), f1 = h2pack(w1a, w1b);
            asm volatile("st.shared.v2.b32 [%0], {%1,%2};"
                         :: "r"(w2fb + (uint32_t)fc * 256 + (uint32_t)lane * 8),
                            "r"(f0), "r"(f1));
        }
    }

    // ---- A fragments from global for this warp's units ----
    uint32_t A[2][8][4];
    hoist_A(A[0], item, pos, b0 + ua / 13, ua % 13, g, t);
    if (nu == 2)
        hoist_A(A[1], item, pos, b0 + ub / 13, ub % 13, g, t);

    asm volatile("cp.async.wait_group 0;" ::: "memory");
    __syncthreads();

    // att as m16n8 C fragments per unit: rows = s, cols = heads (0..3 valid)
    float attC[2][4];
    #pragma unroll
    for (int u = 0; u < 2; u++)
        #pragma unroll
        for (int i = 0; i < 4; i++) attC[u][i] = 0.0f;

    // ---- Barrier-free mainloop: 32 half-sweeps over the resident W1 ----
    if (nu == 2) {
        #pragma unroll 1
        for (int fc = 0; fc < 32; fc++)
            sweep_half<2>(smb + (uint32_t)fc * 4096, w2fb, fc, A, attC, lane);
    } else {
        #pragma unroll 1
        for (int fc = 0; fc < 32; fc++)
            sweep_half<1>(smb + (uint32_t)fc * 4096, w2fb, fc, A, attC, lane);
    }

    // ---- Phase 3: write att from C fragments (t<2 hold heads 0..3) ----
    if (t < 2) {
        #pragma unroll
        for (int i = 0; i < 2; i++) {
            int u = (i == 0) ? ua : ub;
            if (i == 1 && nu == 1) break;
            const int bb = u / 13, mt = u % 13;
            const int s = mt * 16 + g;
            float* ab = atts + bb * NH * ATTP;
            if (s < S_DIM) {
                ab[(2 * t) * ATTP + s]     = attC[i][0];
                ab[(2 * t + 1) * ATTP + s] = attC[i][1];
            }
            if (s + 8 < S_DIM) {
                ab[(2 * t) * ATTP + s + 8]     = attC[i][2];
                ab[(2 * t + 1) * ATTP + s + 8] = attC[i][3];
            }
        }
    }
    __syncthreads();

    // ---- Phase 4: mask + softmax (one warp per (batch, head)) ----
    if (tid < 32 * NH * 2) {
        const int bb = tid >> 7, k = (tid >> 5) & 3, l = tid & 31;
        float* ar = atts + bb * NH * ATTP + k * ATTP;
        const int* mrow = mask + (size_t)(b0 + bb) * S_DIM;
        const float NEGV = -4294967296.0f;
        float mx = -INFINITY;
        for (int s = l; s < S_DIM; s += 32) {
            float v = ar[s];
            if (mrow[s] == 0) v = NEGV;
            ar[s] = v;
            mx = fmaxf(mx, v);
        }
        #pragma unroll
        for (int o = 16; o > 0; o >>= 1) mx = fmaxf(mx, __shfl_xor_sync(0xffffffffu, mx, o));
        float sum = 0.0f;
        for (int s = l; s < S_DIM; s += 32) {
            float e = expf(ar[s] - mx);
            ar[s] = e;
            sum += e;
        }
        #pragma unroll
        for (int o = 16; o > 0; o >>= 1) sum += __shfl_xor_sync(0xffffffffu, sum, o);
        float inv = 1.0f / sum;
        for (int s = l; s < S_DIM; s += 32) ar[s] *= inv;
    }
    __syncthreads();

    // ---- Phase 5: interest; 2 batches x 2 s-slices ----
    {
        const int bb = tid >> 8, rem = tid & 255;
        const int slice = rem >> 7, h = rem & 127;
        const float* ib = item + (size_t)(b0 + bb) * (S_DIM * H_DIM) + h;
        const float* ar = atts + bb * NH * ATTP;
        float a0 = 0.f, a1 = 0.f, a2 = 0.f, a3 = 0.f;
        const int s0 = slice * 100, s1 = s0 + 100;
        #pragma unroll 4
        for (int s = s0; s < s1; s++) {
            float xv = ib[(size_t)s * H_DIM];
            a0 += ar[0 * ATTP + s] * xv;
            a1 += ar[1 * ATTP + s] * xv;
            a2 += ar[2 * ATTP + s] * xv;
            a3 += ar[3 * ATTP + s] * xv;
        }
        if (slice == 1) {
            float* o = outb + bb * 512;
            o[0 * 128 + h] = a0; o[1 * 128 + h] = a1;
            o[2 * 128 + h] = a2; o[3 * 128 + h] = a3;
        }
        __syncthreads();
        if (slice == 0) {
            float* ob = out + (size_t)(b0 + bb) * (NH * H_DIM);
            const float* o = outb + bb * 512;
            ob[0 * H_DIM + h] = a0 + o[0 * 128 + h];
            ob[1 * H_DIM + h] = a1 + o[1 * 128 + h];
            ob[2 * H_DIM + h] = a2 + o[2 * 128 + h];
            ob[3 * H_DIM + h] = a3 + o[3 * 128 + h];
        }
    }
}

extern "C" void kernel_launch(void* const* d_in, const int* in_sizes, int n_in,
                              void* d_out, int out_size)
{
    const float* item = (const float*)d_in[0];
    const int*   mask = (const int*)  d_in[1];
    const float* pos  = (const float*)d_in[2];
    const float* W1   = (const float*)d_in[3];
    const float* W2   = (const float*)d_in[4];
    float* out = (float*)d_out;

    const int B = in_sizes[0] / (S_DIM * H_DIM);

    prep_w1_kernel<<<32, 256>>>(W1);

    cudaFuncSetAttribute(mha_mma_kernel,
                         cudaFuncAttributeMaxDynamicSharedMemorySize, SM_TOTAL);
    mha_mma_kernel<<<B / 2, NT, SM_TOTAL>>>(item, mask, pos, W2, out);
}

// round 16
// speedup vs baseline: 2.0225x; 1.6541x over previous
#include <cuda_runtime.h>
#include <cuda_fp16.h>
#include <math.h>
#include <stdint.h>

#define S_DIM 200
#define H_DIM 128
#define F_DIM 512
#define NH 4
#define ATTP 208
#define NT 512

// smem: [W1 frags 128K][W2 frags 8K][atts 2x][outb 2x][sidx 2x256][cnt/flags]
#define SM_W2F   131072
#define SM_ATT   (SM_W2F + 8192)         // [2][NH][ATTP] floats = 6656 B
#define SM_OUTB  (SM_ATT + 6656)         // [2][512] floats = 4096 B
#define SM_SIDX  (SM_OUTB + 4096)        // [2][256] ints = 2048 B
#define SM_CNT   (SM_SIDX + 2048)        // cnt[2], uflag[2]
#define SM_TOTAL (SM_CNT + 64)           // 152128 B

// W1 in fragment layout, fp16: 256 blocks (blk = fc*8 + kf) * 512 B
__device__ __align__(16) unsigned char gW1f[131072];

static __device__ __forceinline__ uint32_t smem_u32(const void* p) {
    uint32_t a;
    asm("{ .reg .u64 t; cvta.to.shared.u64 t, %1; cvt.u32.u64 %0, t; }" : "=r"(a) : "l"(p));
    return a;
}
static __device__ __forceinline__ uint32_t h2pack(float lo, float hi) {
    __half2 h = __floats2half2_rn(lo, hi);
    return *(uint32_t*)&h;
}
static __device__ __forceinline__ float fast_tanh(float x) {
    float r; asm("tanh.approx.f32 %0, %1;" : "=f"(r) : "f"(x));
    return r;
}
static __device__ __forceinline__ void mma_f16(float* c, const uint32_t* a,
                                               uint32_t b0, uint32_t b1) {
    asm volatile(
        "mma.sync.aligned.m16n8k16.row.col.f32.f16.f16.f32 "
        "{%0,%1,%2,%3}, {%4,%5,%6,%7}, {%8,%9}, {%0,%1,%2,%3};"
        : "+f"(c[0]), "+f"(c[1]), "+f"(c[2]), "+f"(c[3])
        : "r"(a[0]), "r"(a[1]), "r"(a[2]), "r"(a[3]), "r"(b0), "r"(b1));
}

// ---- Prep: W1 f32 [128,512] -> fragment-layout fp16 global buffer (as R14).
__global__ void prep_w1_kernel(const float* __restrict__ W1) {
    int idx = blockIdx.x * blockDim.x + threadIdx.x;   // 8192 threads
    int blk = idx >> 5, lane = idx & 31;
    int g = lane >> 2, t = lane & 3;
    int fc = blk >> 3, kf = blk & 7;
    const float* p = W1 + (size_t)(kf * 16 + 2 * t) * F_DIM + fc * 16 + g;
    uint32_t w0 = h2pack(p[0],             p[F_DIM]);
    uint32_t w1 = h2pack(p[8 * F_DIM],     p[9 * F_DIM]);
    uint32_t w2 = h2pack(p[8],             p[F_DIM + 8]);
    uint32_t w3 = h2pack(p[8 * F_DIM + 8], p[9 * F_DIM + 8]);
    ((uint4*)gW1f)[idx] = make_uint4(w0, w1, w2, w3);
}

// ---- Hoist A fragments for one compacted unit (gathered rows).
static __device__ __forceinline__ void hoist_A(uint32_t A[8][4],
                                               const float* __restrict__ item,
                                               const float* __restrict__ pos,
                                               int b, const int* __restrict__ sidx,
                                               int cnt, int mtl, int g, int t) {
    const int j0 = mtl * 16 + g, j1 = j0 + 8;
    const int s0 = (j0 < cnt) ? sidx[j0] : -1;
    const int s1 = (j1 < cnt) ? sidx[j1] : -1;
    const float* ib = item + (size_t)b * (S_DIM * H_DIM);
    #pragma unroll
    for (int kf = 0; kf < 8; kf++) {
        int e0 = kf * 8 + t;
        if (s0 >= 0) {
            const float2* xr = (const float2*)(ib + s0 * 128);
            const float2* pr = (const float2*)(pos + s0 * 128);
            float2 x0 = xr[e0], p0 = pr[e0];
            float2 x2 = xr[e0 + 4], p2 = pr[e0 + 4];
            A[kf][0] = h2pack(x0.x + p0.x, x0.y + p0.y);
            A[kf][2] = h2pack(x2.x + p2.x, x2.y + p2.y);
        } else { A[kf][0] = 0u; A[kf][2] = 0u; }
        if (s1 >= 0) {
            const float2* xr = (const float2*)(ib + s1 * 128);
            const float2* pr = (const float2*)(pos + s1 * 128);
            float2 x1 = xr[e0], p1 = pr[e0];
            float2 x3 = xr[e0 + 4], p3 = pr[e0 + 4];
            A[kf][1] = h2pack(x1.x + p1.x, x1.y + p1.y);
            A[kf][3] = h2pack(x3.x + p3.x, x3.y + p3.y);
        } else { A[kf][1] = 0u; A[kf][3] = 0u; }
    }
}

// ---- One half-sweep (16 N-cols = one f-chunk fc) for NU units.
template<int NU>
static __device__ __forceinline__ void sweep_half(uint32_t base0, uint32_t w2fb,
                                                  int fc,
                                                  const uint32_t A[2][8][4],
                                                  float attC[2][4],
                                                  int lane) {
    float acc[NU][2][4];
    #pragma unroll
    for (int u = 0; u < NU; u++)
        #pragma unroll
        for (int nf = 0; nf < 2; nf++)
            #pragma unroll
            for (int i = 0; i < 4; i++) acc[u][nf][i] = 0.0f;

    uint32_t base = base0 + (uint32_t)lane * 16;
    #pragma unroll
    for (int kf = 0; kf < 8; kf++) {
        uint32_t x0, x1, x2, x3;
        asm volatile("ld.shared.v4.b32 {%0,%1,%2,%3}, [%4];"
                     : "=r"(x0), "=r"(x1), "=r"(x2), "=r"(x3)
                     : "r"(base + (uint32_t)kf * 512));
        #pragma unroll
        for (int u = 0; u < NU; u++) {
            mma_f16(acc[u][0], A[u][kf], x0, x1);
            mma_f16(acc[u][1], A[u][kf], x2, x3);
        }
    }

    uint32_t bf0, bf1;
    asm volatile("ld.shared.v2.b32 {%0,%1}, [%2];"
                 : "=r"(bf0), "=r"(bf1)
                 : "r"(w2fb + (uint32_t)fc * 256 + (uint32_t)lane * 8));

    #pragma unroll
    for (int u = 0; u < NU; u++) {
        uint32_t Af[4];
        Af[0] = h2pack(fast_tanh(acc[u][0][0]), fast_tanh(acc[u][0][1]));
        Af[1] = h2pack(fast_tanh(acc[u][0][2]), fast_tanh(acc[u][0][3]));
        Af[2] = h2pack(fast_tanh(acc[u][1][0]), fast_tanh(acc[u][1][1]));
        Af[3] = h2pack(fast_tanh(acc[u][1][2]), fast_tanh(acc[u][1][3]));
        mma_f16(attC[u], Af, bf0, bf1);
    }
}

__global__ __launch_bounds__(NT, 1)
void mha_mma_kernel(const float* __restrict__ item,
                    const int*   __restrict__ mask,
                    const float* __restrict__ pos,
                    const float* __restrict__ W2,
                    float* __restrict__ out)
{
    extern __shared__ char smem[];
    const uint32_t smb = smem_u32(smem);
    float* atts  = (float*)(smem + SM_ATT);   // compacted att [2][NH][ATTP]
    float* outb  = (float*)(smem + SM_OUTB);  // [2][512]
    int*   sidxs = (int*)(smem + SM_SIDX);    // [2][256]
    int*   cnts  = (int*)(smem + SM_CNT);     // cnt[2]
    int*   uflg  = cnts + 2;                  // uniform flag[2]

    const int tid = threadIdx.x, wid = tid >> 5, lane = tid & 31;
    const int g = lane >> 2, t = lane & 3;
    const int b0 = 2 * blockIdx.x;
    const uint32_t w2fb = smb + SM_W2F;

    // ---- Stage all of W1 (fragment fp16) via cp.async ----
    {
        const char* gsrc = (const char*)gW1f;
        #pragma unroll
        for (int i = 0; i < 16; i++) {
            uint32_t off = (uint32_t)(i * NT + tid) * 16;
            asm volatile("cp.async.cg.shared.global [%0], [%1], 16;"
                         :: "r"(smb + off), "l"(gsrc + off));
        }
        asm volatile("cp.async.commit_group;" ::: "memory");
    }

    // ---- W2 -> n8k16 B-fragment buffer (warp w handles fc = 2w, 2w+1) ----
    {
        #pragma unroll
        for (int i = 0; i < 2; i++) {
            int fc = wid * 2 + i;
            float w0a = 0.f, w0b = 0.f, w1a = 0.f, w1b = 0.f;
            if (g < NH) {
                int fb = fc * 16;
                w0a = W2[(fb + 2 * t) * NH + g];
                w0b = W2[(fb + 2 * t + 1) * NH + g];
                w1a = W2[(fb + 8 + 2 * t) * NH + g];
                w1b = W2[(fb + 9 + 2 * t) * NH + g];
            }
            uint32_t f0 = h2pack(w0a, w0b), f1 = h2pack(w1a, w1b);
            asm volatile("st.shared.v2.b32 [%0], {%1,%2};"
                         :: "r"(w2fb + (uint32_t)fc * 256 + (uint32_t)lane * 8),
                            "r"(f0), "r"(f1));
        }
    }

    // ---- Compaction: warps 0,1 build unmasked index list per batch ----
    if (wid < 2) {
        const int* mrow = mask + (size_t)(b0 + wid) * S_DIM;
        int* sd = sidxs + wid * 256;
        int base = 0;
        #pragma unroll
        for (int c = 0; c < 7; c++) {
            int s = c * 32 + lane;
            int m = (s < S_DIM) ? mrow[s] : 0;
            unsigned bal = __ballot_sync(0xffffffffu, m != 0);
            if (m != 0) sd[base + __popc(bal & ((1u << lane) - 1u))] = s;
            base += __popc(bal);
        }
        int uni = (base == 0);
        if (uni) {   // all masked: reference softmax is uniform over ALL s
            for (int s = lane; s < S_DIM; s += 32) sd[s] = s;
            base = S_DIM;
        }
        if (lane == 0) { cnts[wid] = base; uflg[wid] = uni; }
    }
    __syncthreads();   // sidx/cnt visible (also W2 frags)

    const int cnt0 = cnts[0], cnt1 = cnts[1];
    const int nmt0 = (cnt0 + 15) >> 4, nmt1 = (cnt1 + 15) >> 4;
    const int nunits = nmt0 + nmt1;
    const int ua = (wid < nunits) ? wid : -1;
    const int ub = (wid + 16 < nunits) ? wid + 16 : -1;

    // ---- A fragments (gathered) for this warp's units ----
    uint32_t A[2][8][4];
    int ubb[2], umt[2];
    if (ua >= 0) {
        ubb[0] = (ua >= nmt0); umt[0] = ua - (ubb[0] ? nmt0 : 0);
        hoist_A(A[0], item, pos, b0 + ubb[0], sidxs + ubb[0] * 256,
                ubb[0] ? cnt1 : cnt0, umt[0], g, t);
    }
    if (ub >= 0) {
        ubb[1] = (ub >= nmt0); umt[1] = ub - (ubb[1] ? nmt0 : 0);
        hoist_A(A[1], item, pos, b0 + ubb[1], sidxs + ubb[1] * 256,
                ubb[1] ? cnt1 : cnt0, umt[1], g, t);
    }

    asm volatile("cp.async.wait_group 0;" ::: "memory");
    __syncthreads();

    float attC[2][4];
    #pragma unroll
    for (int u = 0; u < 2; u++)
        #pragma unroll
        for (int i = 0; i < 4; i++) attC[u][i] = 0.0f;

    // ---- Barrier-free mainloop over resident W1 ----
    if (ua >= 0) {
        if (ub >= 0) {
            #pragma unroll 1
            for (int fc = 0; fc < 32; fc++)
                sweep_half<2>(smb + (uint32_t)fc * 4096, w2fb, fc, A, attC, lane);
        } else {
            #pragma unroll 1
            for (int fc = 0; fc < 32; fc++)
                sweep_half<1>(smb + (uint32_t)fc * 4096, w2fb, fc, A, attC, lane);
        }
    }

    // ---- Writeback att C fragments into compacted att array ----
    if (t < 2) {
        #pragma unroll
        for (int i = 0; i < 2; i++) {
            if (i == 0 ? (ua < 0) : (ub < 0)) break;
            const int j = umt[i] * 16 + g;
            float* ab = atts + ubb[i] * NH * ATTP;
            ab[(2 * t) * ATTP + j]         = attC[i][0];
            ab[(2 * t + 1) * ATTP + j]     = attC[i][1];
            ab[(2 * t) * ATTP + j + 8]     = attC[i][2];
            ab[(2 * t + 1) * ATTP + j + 8] = attC[i][3];
        }
    }
    __syncthreads();

    // ---- Softmax over compacted set (one warp per (batch, head)) ----
    if (tid < 32 * NH * 2) {
        const int bb = tid >> 7, k = (tid >> 5) & 3, l = tid & 31;
        float* ar = atts + bb * NH * ATTP + k * ATTP;
        const int cnt = cnts[bb];
        if (uflg[bb]) {
            float u = 1.0f / (float)S_DIM;
            for (int j = l; j < cnt; j += 32) ar[j] = u;
        } else {
            float mx = -INFINITY;
            for (int j = l; j < cnt; j += 32) mx = fmaxf(mx, ar[j]);
            #pragma unroll
            for (int o = 16; o > 0; o >>= 1) mx = fmaxf(mx, __shfl_xor_sync(0xffffffffu, mx, o));
            float sum = 0.0f;
            for (int j = l; j < cnt; j += 32) {
                float e = expf(ar[j] - mx);
                ar[j] = e;
                sum += e;
            }
            #pragma unroll
            for (int o = 16; o > 0; o >>= 1) sum += __shfl_xor_sync(0xffffffffu, sum, o);
            float inv = 1.0f / sum;
            for (int j = l; j < cnt; j += 32) ar[j] *= inv;
        }
    }
    __syncthreads();

    // ---- Interest over compacted rows; 2 batches x 2 j-slices ----
    {
        const int bb = tid >> 8, rem = tid & 255;
        const int slice = rem >> 7, h = rem & 127;
        const float* ib = item + (size_t)(b0 + bb) * (S_DIM * H_DIM) + h;
        const float* ar = atts + bb * NH * ATTP;
        const int* sd = sidxs + bb * 256;
        const int cnt = cnts[bb];
        const int j0 = slice ? (cnt >> 1) : 0;
        const int j1 = slice ? cnt : (cnt >> 1);
        float a0 = 0.f, a1 = 0.f, a2 = 0.f, a3 = 0.f;
        for (int j = j0; j < j1; j++) {
            float xv = ib[(size_t)sd[j] * H_DIM];
            a0 += ar[0 * ATTP + j] * xv;
            a1 += ar[1 * ATTP + j] * xv;
            a2 += ar[2 * ATTP + j] * xv;
            a3 += ar[3 * ATTP + j] * xv;
        }
        if (slice == 1) {
            float* o = outb + bb * 512;
            o[0 * 128 + h] = a0; o[1 * 128 + h] = a1;
            o[2 * 128 + h] = a2; o[3 * 128 + h] = a3;
        }
        __syncthreads();
        if (slice == 0) {
            float* ob = out + (size_t)(b0 + bb) * (NH * H_DIM);
            const float* o = outb + bb * 512;
            ob[0 * H_DIM + h] = a0 + o[0 * 128 + h];
            ob[1 * H_DIM + h] = a1 + o[1 * 128 + h];
            ob[2 * H_DIM + h] = a2 + o[2 * 128 + h];
            ob[3 * H_DIM + h] = a3 + o[3 * 128 + h];
        }
    }
}

extern "C" void kernel_launch(void* const* d_in, const int* in_sizes, int n_in,
                              void* d_out, int out_size)
{
    const float* item = (const float*)d_in[0];
    const int*   mask = (const int*)  d_in[1];
    const float* pos  = (const float*)d_in[2];
    const float* W1   = (const float*)d_in[3];
    const float* W2   = (const float*)d_in[4];
    float* out = (float*)d_out;

    const int B = in_sizes[0] / (S_DIM * H_DIM);

    prep_w1_kernel<<<32, 256>>>(W1);

    cudaFuncSetAttribute(mha_mma_kernel,
                         cudaFuncAttributeMaxDynamicSharedMemorySize, SM_TOTAL);
    mha_mma_kernel<<<B / 2, NT, SM_TOTAL>>>(item, mask, pos, W2, out);
}

// round 17
// speedup vs baseline: 2.1890x; 1.0823x over previous
#include <cuda_runtime.h>
#include <cuda_fp16.h>
#include <math.h>
#include <stdint.h>

#define S_DIM 200
#define H_DIM 128
#define F_DIM 512
#define NH 4
#define ATTP 208
#define NT 512
#define NB 4                 // batches per CTA

// smem: [W1 frags 128K][W2 frags 8K][atts 4x][sidx 4x256][cnt/flags]
#define SM_W2F   131072
#define SM_ATT   (SM_W2F + 8192)          // [4][NH][ATTP] floats = 13312 B
#define SM_SIDX  (SM_ATT + 13312)         // [4][256] ints = 4096 B
#define SM_CNT   (SM_SIDX + 4096)         // cnt[4], uflag[4]
#define SM_TOTAL (SM_CNT + 64)            // 156544 B

// W1 in fragment layout, fp16: 256 blocks (blk = fc*8 + kf) * 512 B
__device__ __align__(16) unsigned char gW1f[131072];

static __device__ __forceinline__ uint32_t smem_u32(const void* p) {
    uint32_t a;
    asm("{ .reg .u64 t; cvta.to.shared.u64 t, %1; cvt.u32.u64 %0, t; }" : "=r"(a) : "l"(p));
    return a;
}
static __device__ __forceinline__ uint32_t h2pack(float lo, float hi) {
    __half2 h = __floats2half2_rn(lo, hi);
    return *(uint32_t*)&h;
}
static __device__ __forceinline__ float fast_tanh(float x) {
    float r; asm("tanh.approx.f32 %0, %1;" : "=f"(r) : "f"(x));
    return r;
}
static __device__ __forceinline__ void mma_f16(float* c, const uint32_t* a,
                                               uint32_t b0, uint32_t b1) {
    asm volatile(
        "mma.sync.aligned.m16n8k16.row.col.f32.f16.f16.f32 "
        "{%0,%1,%2,%3}, {%4,%5,%6,%7}, {%8,%9}, {%0,%1,%2,%3};"
        : "+f"(c[0]), "+f"(c[1]), "+f"(c[2]), "+f"(c[3])
        : "r"(a[0]), "r"(a[1]), "r"(a[2]), "r"(a[3]), "r"(b0), "r"(b1));
}

// ---- Prep: W1 f32 [128,512] -> fragment-layout fp16 global buffer.
__global__ void prep_w1_kernel(const float* __restrict__ W1) {
    int idx = blockIdx.x * blockDim.x + threadIdx.x;   // 8192 threads
    int blk = idx >> 5, lane = idx & 31;
    int g = lane >> 2, t = lane & 3;
    int fc = blk >> 3, kf = blk & 7;
    const float* p = W1 + (size_t)(kf * 16 + 2 * t) * F_DIM + fc * 16 + g;
    uint32_t w0 = h2pack(p[0],             p[F_DIM]);
    uint32_t w1 = h2pack(p[8 * F_DIM],     p[9 * F_DIM]);
    uint32_t w2 = h2pack(p[8],             p[F_DIM + 8]);
    uint32_t w3 = h2pack(p[8 * F_DIM + 8], p[9 * F_DIM + 8]);
    ((uint4*)gW1f)[idx] = make_uint4(w0, w1, w2, w3);
}

// ---- Hoist A fragments for one compacted unit (gathered rows).
static __device__ __forceinline__ void hoist_A(uint32_t A[8][4],
                                               const float* __restrict__ item,
                                               const float* __restrict__ pos,
                                               int b, const int* __restrict__ sidx,
                                               int cnt, int mtl, int g, int t) {
    const int j0 = mtl * 16 + g, j1 = j0 + 8;
    const int s0 = (j0 < cnt) ? sidx[j0] : -1;
    const int s1 = (j1 < cnt) ? sidx[j1] : -1;
    const float* ib = item + (size_t)b * (S_DIM * H_DIM);
    #pragma unroll
    for (int kf = 0; kf < 8; kf++) {
        int e0 = kf * 8 + t;
        if (s0 >= 0) {
            const float2* xr = (const float2*)(ib + s0 * 128);
            const float2* pr = (const float2*)(pos + s0 * 128);
            float2 x0 = xr[e0], p0 = pr[e0];
            float2 x2 = xr[e0 + 4], p2 = pr[e0 + 4];
            A[kf][0] = h2pack(x0.x + p0.x, x0.y + p0.y);
            A[kf][2] = h2pack(x2.x + p2.x, x2.y + p2.y);
        } else { A[kf][0] = 0u; A[kf][2] = 0u; }
        if (s1 >= 0) {
            const float2* xr = (const float2*)(ib + s1 * 128);
            const float2* pr = (const float2*)(pos + s1 * 128);
            float2 x1 = xr[e0], p1 = pr[e0];
            float2 x3 = xr[e0 + 4], p3 = pr[e0 + 4];
            A[kf][1] = h2pack(x1.x + p1.x, x1.y + p1.y);
            A[kf][3] = h2pack(x3.x + p3.x, x3.y + p3.y);
        } else { A[kf][1] = 0u; A[kf][3] = 0u; }
    }
}

// ---- One half-sweep (16 N-cols = one f-chunk fc) for NU units.
template<int NU>
static __device__ __forceinline__ void sweep_half(uint32_t base0, uint32_t w2fb,
                                                  int fc,
                                                  const uint32_t A[2][8][4],
                                                  float attC[2][4],
                                                  int lane) {
    float acc[NU][2][4];
    #pragma unroll
    for (int u = 0; u < NU; u++)
        #pragma unroll
        for (int nf = 0; nf < 2; nf++)
            #pragma unroll
            for (int i = 0; i < 4; i++) acc[u][nf][i] = 0.0f;

    uint32_t base = base0 + (uint32_t)lane * 16;
    #pragma unroll
    for (int kf = 0; kf < 8; kf++) {
        uint32_t x0, x1, x2, x3;
        asm volatile("ld.shared.v4.b32 {%0,%1,%2,%3}, [%4];"
                     : "=r"(x0), "=r"(x1), "=r"(x2), "=r"(x3)
                     : "r"(base + (uint32_t)kf * 512));
        #pragma unroll
        for (int u = 0; u < NU; u++) {
            mma_f16(acc[u][0], A[u][kf], x0, x1);
            mma_f16(acc[u][1], A[u][kf], x2, x3);
        }
    }

    uint32_t bf0, bf1;
    asm volatile("ld.shared.v2.b32 {%0,%1}, [%2];"
                 : "=r"(bf0), "=r"(bf1)
                 : "r"(w2fb + (uint32_t)fc * 256 + (uint32_t)lane * 8));

    #pragma unroll
    for (int u = 0; u < NU; u++) {
        uint32_t Af[4];
        Af[0] = h2pack(fast_tanh(acc[u][0][0]), fast_tanh(acc[u][0][1]));
        Af[1] = h2pack(fast_tanh(acc[u][0][2]), fast_tanh(acc[u][0][3]));
        Af[2] = h2pack(fast_tanh(acc[u][1][0]), fast_tanh(acc[u][1][1]));
        Af[3] = h2pack(fast_tanh(acc[u][1][2]), fast_tanh(acc[u][1][3]));
        mma_f16(attC[u], Af, bf0, bf1);
    }
}

__global__ __launch_bounds__(NT, 1)
void mha_mma_kernel(const float* __restrict__ item,
                    const int*   __restrict__ mask,
                    const float* __restrict__ pos,
                    const float* __restrict__ W2,
                    float* __restrict__ out)
{
    extern __shared__ char smem[];
    const uint32_t smb = smem_u32(smem);
    float* atts  = (float*)(smem + SM_ATT);   // compacted att [NB][NH][ATTP]
    int*   sidxs = (int*)(smem + SM_SIDX);    // [NB][256]
    int*   cnts  = (int*)(smem + SM_CNT);     // cnt[NB]
    int*   uflg  = cnts + NB;                 // uniform flag[NB]

    const int tid = threadIdx.x, wid = tid >> 5, lane = tid & 31;
    const int g = lane >> 2, t = lane & 3;
    const int b0 = NB * blockIdx.x;
    const uint32_t w2fb = smb + SM_W2F;

    // ---- Stage all of W1 (fragment fp16) via cp.async ----
    {
        const char* gsrc = (const char*)gW1f;
        #pragma unroll
        for (int i = 0; i < 16; i++) {
            uint32_t off = (uint32_t)(i * NT + tid) * 16;
            asm volatile("cp.async.cg.shared.global [%0], [%1], 16;"
                         :: "r"(smb + off), "l"(gsrc + off));
        }
        asm volatile("cp.async.commit_group;" ::: "memory");
    }

    // ---- W2 -> n8k16 B-fragment buffer (warp w handles fc = 2w, 2w+1) ----
    {
        #pragma unroll
        for (int i = 0; i < 2; i++) {
            int fc = wid * 2 + i;
            float w0a = 0.f, w0b = 0.f, w1a = 0.f, w1b = 0.f;
            if (g < NH) {
                int fb = fc * 16;
                w0a = W2[(fb + 2 * t) * NH + g];
                w0b = W2[(fb + 2 * t + 1) * NH + g];
                w1a = W2[(fb + 8 + 2 * t) * NH + g];
                w1b = W2[(fb + 9 + 2 * t) * NH + g];
            }
            uint32_t f0 = h2pack(w0a, w0b), f1 = h2pack(w1a, w1b);
            asm volatile("st.shared.v2.b32 [%0], {%1,%2};"
                         :: "r"(w2fb + (uint32_t)fc * 256 + (uint32_t)lane * 8),
                            "r"(f0), "r"(f1));
        }
    }

    // ---- Compaction: warps 0..3 build unmasked index list per batch ----
    if (wid < NB) {
        const int* mrow = mask + (size_t)(b0 + wid) * S_DIM;
        int* sd = sidxs + wid * 256;
        int base = 0;
        #pragma unroll
        for (int c = 0; c < 7; c++) {
            int s = c * 32 + lane;
            int m = (s < S_DIM) ? mrow[s] : 0;
            unsigned bal = __ballot_sync(0xffffffffu, m != 0);
            if (m != 0) sd[base + __popc(bal & ((1u << lane) - 1u))] = s;
            base += __popc(bal);
        }
        int uni = (base == 0);
        if (uni) {   // all masked: reference softmax is uniform over ALL s
            for (int s = lane; s < S_DIM; s += 32) sd[s] = s;
            base = S_DIM;
        }
        if (lane == 0) { cnts[wid] = base; uflg[wid] = uni; }
    }
    __syncthreads();   // sidx/cnt visible (also W2 frags)

    const int c0 = cnts[0], c1 = cnts[1], c2 = cnts[2], c3 = cnts[3];
    const int n0 = (c0 + 15) >> 4, n1 = (c1 + 15) >> 4;
    const int n2 = (c2 + 15) >> 4, n3 = (c3 + 15) >> 4;
    const int o1 = n0, o2 = n0 + n1, o3 = n0 + n1 + n2;
    const int nunits = o3 + n3;

    asm volatile("cp.async.wait_group 0;" ::: "memory");
    __syncthreads();

    // ---- Pass loop over units (32 warp-slots per pass; 1 pass typical) ----
    #pragma unroll 1
    for (int pbase = 0; pbase < nunits; pbase += 32) {
        const int ua = pbase + wid, ub = pbase + wid + 16;
        const bool va = (ua < nunits), vb = (ub < nunits);

        uint32_t A[2][8][4];
        int ubb[2] = {0, 0}, umt[2] = {0, 0};
        if (va) {
            int bb = (ua >= o1) + (ua >= o2) + (ua >= o3);
            int off = (bb == 0) ? 0 : (bb == 1) ? o1 : (bb == 2) ? o2 : o3;
            int cn = (bb == 0) ? c0 : (bb == 1) ? c1 : (bb == 2) ? c2 : c3;
            ubb[0] = bb; umt[0] = ua - off;
            hoist_A(A[0], item, pos, b0 + bb, sidxs + bb * 256, cn, umt[0], g, t);
        }
        if (vb) {
            int bb = (ub >= o1) + (ub >= o2) + (ub >= o3);
            int off = (bb == 0) ? 0 : (bb == 1) ? o1 : (bb == 2) ? o2 : o3;
            int cn = (bb == 0) ? c0 : (bb == 1) ? c1 : (bb == 2) ? c2 : c3;
            ubb[1] = bb; umt[1] = ub - off;
            hoist_A(A[1], item, pos, b0 + bb, sidxs + bb * 256, cn, umt[1], g, t);
        }

        float attC[2][4];
        #pragma unroll
        for (int u = 0; u < 2; u++)
            #pragma unroll
            for (int i = 0; i < 4; i++) attC[u][i] = 0.0f;

        if (va) {
            if (vb) {
                #pragma unroll 1
                for (int fc = 0; fc < 32; fc++)
                    sweep_half<2>(smb + (uint32_t)fc * 4096, w2fb, fc, A, attC, lane);
            } else {
                #pragma unroll 1
                for (int fc = 0; fc < 32; fc++)
                    sweep_half<1>(smb + (uint32_t)fc * 4096, w2fb, fc, A, attC, lane);
            }
        }

        // writeback att C fragments into compacted att array
        if (t < 2) {
            #pragma unroll
            for (int i = 0; i < 2; i++) {
                if (i == 0 ? !va : !vb) break;
                const int j = umt[i] * 16 + g;
                float* ab = atts + ubb[i] * NH * ATTP;
                ab[(2 * t) * ATTP + j]         = attC[i][0];
                ab[(2 * t + 1) * ATTP + j]     = attC[i][1];
                ab[(2 * t) * ATTP + j + 8]     = attC[i][2];
                ab[(2 * t + 1) * ATTP + j + 8] = attC[i][3];
            }
        }
    }
    __syncthreads();

    // ---- Softmax over compacted set (one warp per (batch, head)) ----
    {
        const int bb = tid >> 7, k = (tid >> 5) & 3, l = tid & 31;
        float* ar = atts + bb * NH * ATTP + k * ATTP;
        const int cnt = cnts[bb];
        if (uflg[bb]) {
            float u = 1.0f / (float)S_DIM;
            for (int j = l; j < cnt; j += 32) ar[j] = u;
        } else {
            float mx = -INFINITY;
            for (int j = l; j < cnt; j += 32) mx = fmaxf(mx, ar[j]);
            #pragma unroll
            for (int o = 16; o > 0; o >>= 1) mx = fmaxf(mx, __shfl_xor_sync(0xffffffffu, mx, o));
            float sum = 0.0f;
            for (int j = l; j < cnt; j += 32) {
                float e = expf(ar[j] - mx);
                ar[j] = e;
                sum += e;
            }
            #pragma unroll
            for (int o = 16; o > 0; o >>= 1) sum += __shfl_xor_sync(0xffffffffu, sum, o);
            float inv = 1.0f / sum;
            for (int j = l; j < cnt; j += 32) ar[j] *= inv;
        }
    }
    __syncthreads();

    // ---- Interest over compacted rows; thread = (batch, h) ----
    {
        const int bb = tid >> 7, h = tid & 127;
        const float* ib = item + (size_t)(b0 + bb) * (S_DIM * H_DIM) + h;
        const float* ar = atts + bb * NH * ATTP;
        const int* sd = sidxs + bb * 256;
        const int cnt = cnts[bb];
        float a0 = 0.f, a1 = 0.f, a2 = 0.f, a3 = 0.f;
        #pragma unroll 4
        for (int j = 0; j < cnt; j++) {
            float xv = ib[(size_t)sd[j] * H_DIM];
            a0 += ar[0 * ATTP + j] * xv;
            a1 += ar[1 * ATTP + j] * xv;
            a2 += ar[2 * ATTP + j] * xv;
            a3 += ar[3 * ATTP + j] * xv;
        }
        float* ob = out + (size_t)(b0 + bb) * (NH * H_DIM);
        ob[0 * H_DIM + h] = a0;
        ob[1 * H_DIM + h] = a1;
        ob[2 * H_DIM + h] = a2;
        ob[3 * H_DIM + h] = a3;
    }
}

extern "C" void kernel_launch(void* const* d_in, const int* in_sizes, int n_in,
                              void* d_out, int out_size)
{
    const float* item = (const float*)d_in[0];
    const int*   mask = (const int*)  d_in[1];
    const float* pos  = (const float*)d_in[2];
    const float* W1   = (const float*)d_in[3];
    const float* W2   = (const float*)d_in[4];
    float* out = (float*)d_out;

    const int B = in_sizes[0] / (S_DIM * H_DIM);

    prep_w1_kernel<<<32, 256>>>(W1);

    cudaFuncSetAttribute(mha_mma_kernel,
                         cudaFuncAttributeMaxDynamicSharedMemorySize, SM_TOTAL);
    mha_mma_kernel<<<B / NB, NT, SM_TOTAL>>>(item, mask, pos, W2, out);
}